// round 10
// baseline (speedup 1.0000x reference)
#include <cuda_runtime.h>
#include <cstdint>

#define SEQ   2048
#define HID   64
#define NROWS 2048
#define EPSC  1e-6f
#define WPB   4            // warps per block -> 1 per SMSP
#define NT    (WPB * 32)   // 128 threads
#define RPW   4            // rows per warp
#define NBLK  (NROWS / (RPW * WPB))   // 128 blocks, 1 per SM

__device__ __forceinline__ unsigned long long ffma2(unsigned long long a,
                                                    unsigned long long b,
                                                    unsigned long long c) {
    unsigned long long d;
    asm("fma.rn.f32x2 %0, %1, %2, %3;" : "=l"(d) : "l"(a), "l"(b), "l"(c));
    return d;
}
__device__ __forceinline__ float flo(unsigned long long a) {
    return __uint_as_float((unsigned)a);
}
__device__ __forceinline__ float fhi(unsigned long long a) {
    return __uint_as_float((unsigned)(a >> 32));
}
__device__ __forceinline__ unsigned long long packlo(float x) {
    return (unsigned long long)__float_as_uint(x);   // hi = +0.0f
}

__global__ void __launch_bounds__(NT, 1)
rnn_garch_kernel(const float* __restrict__ resid,
                 const float* __restrict__ Wih,
                 const float* __restrict__ bih,
                 const float* __restrict__ Whh,
                 const float* __restrict__ bhh,
                 const float* __restrict__ fcw,
                 const float* __restrict__ fcb_p,
                 float* __restrict__ out) {
    // [warp][buffer][row-in-warp][64]
    __shared__ __align__(16) float hsh[WPB][2][RPW][HID];

    const int lane = threadIdx.x & 31;
    const int wid  = threadIdx.x >> 5;
    const int gw   = blockIdx.x * WPB + wid;
    const int j  = lane;
    const int j2 = lane + 32;

    // ---- W_hh rows j, j+32 as packed f32x2 (shared by all 4 rows) ----
    unsigned long long W0[32], W1[32];
    {
        const ulonglong2* wr0 = reinterpret_cast<const ulonglong2*>(Whh + j  * HID);
        const ulonglong2* wr1 = reinterpret_cast<const ulonglong2*>(Whh + j2 * HID);
#pragma unroll
        for (int i = 0; i < 16; ++i) {
            ulonglong2 a = wr0[i]; W0[2 * i] = a.x; W0[2 * i + 1] = a.y;
            ulonglong2 c = wr1[i]; W1[2 * i] = c.x; W1[2 * i + 1] = c.y;
        }
    }
    const float wih_e0 = Wih[2 * j],  wih_s0 = Wih[2 * j + 1];
    const float wih_e1 = Wih[2 * j2], wih_s1 = Wih[2 * j2 + 1];
    const float bias0  = bih[j]  + bhh[j];
    const float bias1  = bih[j2] + bhh[j2];

    // z-trick constants: z_t = g.h_{t-1} + a*e2_t + b*sig_{t-1} + c
    float a_c, b_c, c_c;
    {
        const float fcj = fcw[j], fcj2 = fcw[j2];
        float pa = fcj * wih_e0 + fcj2 * wih_e1;
        float pb = fcj * wih_s0 + fcj2 * wih_s1;
        float pc = fcj * bias0  + fcj2 * bias1;
#pragma unroll
        for (int o = 16; o; o >>= 1) {
            pa += __shfl_xor_sync(0xffffffffu, pa, o);
            pb += __shfl_xor_sync(0xffffffffu, pb, o);
            pc += __shfl_xor_sync(0xffffffffu, pc, o);
        }
        a_c = pa; b_c = pb; c_c = pc + fcb_p[0];
    }

    // g = W_hh^T fc
    float g0 = 0.f, g1 = 0.f;
#pragma unroll 8
    for (int l = 0; l < HID; ++l) {
        const float f = fcw[l];
        g0 = fmaf(f, Whh[l * HID + j],  g0);
        g1 = fmaf(f, Whh[l * HID + j2], g1);
    }

    const float* rrow[RPW];
    float*       orow[RPW];
#pragma unroll
    for (int r = 0; r < RPW; ++r) {
        const int row = gw * RPW + r;
        rrow[r] = resid + (size_t)row * SEQ;
        orow[r] = out   + (size_t)row * SEQ;
    }

    // ---- sigma0 per row ----
    float sig[RPW];
    {
        float s1[RPW], s2[RPW];
#pragma unroll
        for (int r = 0; r < RPW; ++r) { s1[r] = 0.f; s2[r] = 0.f; }
        for (int i = lane; i < SEQ / 4; i += 32) {
#pragma unroll
            for (int r = 0; r < RPW; ++r) {
                float4 v = reinterpret_cast<const float4*>(rrow[r])[i];
                s1[r] += (v.x + v.y) + (v.z + v.w);
                s2[r] += v.x * v.x + v.y * v.y + v.z * v.z + v.w * v.w;
            }
        }
#pragma unroll
        for (int o = 16; o; o >>= 1) {
#pragma unroll
            for (int r = 0; r < RPW; ++r) {
                s1[r] += __shfl_xor_sync(0xffffffffu, s1[r], o);
                s2[r] += __shfl_xor_sync(0xffffffffu, s2[r], o);
            }
        }
#pragma unroll
        for (int r = 0; r < RPW; ++r)
            sig[r] = (s2[r] - s1[r] * s1[r] * (1.0f / SEQ)) * (1.0f / (SEQ - 1));
    }

#pragma unroll
    for (int r = 0; r < RPW; ++r) {
        hsh[wid][0][r][j] = 0.f; hsh[wid][0][r][j2] = 0.f;
    }
    __syncwarp();

    float h0[RPW], h1[RPW];          // register copy of h_{t-1}
    float rbuf[RPW], rnext[RPW], sbuf[RPW];
#pragma unroll
    for (int r = 0; r < RPW; ++r) {
        h0[r] = 0.f; h1[r] = 0.f;
        sbuf[r] = sig[r];
        rbuf[r] = 0.f;
        rnext[r] = rrow[r][lane];
    }

    int cur = 0;
    for (int t = 1; t < SEQ; ++t) {
        const int tm1 = t - 1;
        const int sl  = tm1 & 31;

        if (sl == 0) {
#pragma unroll
            for (int r = 0; r < RPW; ++r) rbuf[r] = rnext[r];
        }
        float e2[RPW];
#pragma unroll
        for (int r = 0; r < RPW; ++r) {
            const float e = __shfl_sync(0xffffffffu, rbuf[r], sl);
            e2[r] = e * e;
        }
        if (sl == 16) {
            const int base = (tm1 & ~31) + 32;
            if (base < SEQ) {
#pragma unroll
                for (int r = 0; r < RPW; ++r) rnext[r] = rrow[r][base + lane];
            }
        }

        // ---- matvec: 4 rows x 2 outputs, one chain each (depth 32) ----
        unsigned long long acc0[RPW], acc1[RPW];
#pragma unroll
        for (int r = 0; r < RPW; ++r) {
            acc0[r] = packlo(fmaf(e2[r], wih_e0, fmaf(sig[r], wih_s0, bias0)));
            acc1[r] = packlo(fmaf(e2[r], wih_e1, fmaf(sig[r], wih_s1, bias1)));
        }
        const ulonglong2* hb[RPW];
#pragma unroll
        for (int r = 0; r < RPW; ++r)
            hb[r] = reinterpret_cast<const ulonglong2*>(&hsh[wid][cur][r][0]);
#pragma unroll
        for (int p = 0; p < 16; ++p) {
#pragma unroll
            for (int r = 0; r < RPW; ++r) {
                const ulonglong2 hv = hb[r][p];
                acc0[r] = ffma2(hv.x, W0[2 * p],     acc0[r]);
                acc1[r] = ffma2(hv.x, W1[2 * p],     acc1[r]);
                acc0[r] = ffma2(hv.y, W0[2 * p + 1], acc0[r]);
                acc1[r] = ffma2(hv.y, W1[2 * p + 1], acc1[r]);
            }
        }

        // z shuffle-reduce from h_{t-1} registers (overlaps fma stream)
        float zp[RPW];
#pragma unroll
        for (int r = 0; r < RPW; ++r) zp[r] = fmaf(g0, h0[r], g1 * h1[r]);
#pragma unroll
        for (int o = 16; o; o >>= 1) {
#pragma unroll
            for (int r = 0; r < RPW; ++r)
                zp[r] += __shfl_xor_sync(0xffffffffu, zp[r], o);
        }

        // finalize h_t and publish
#pragma unroll
        for (int r = 0; r < RPW; ++r) {
            h0[r] = flo(acc0[r]) + fhi(acc0[r]);
            h1[r] = flo(acc1[r]) + fhi(acc1[r]);
            hsh[wid][cur ^ 1][r][j]  = h0[r];
            hsh[wid][cur ^ 1][r][j2] = h1[r];
        }
        __syncwarp();
        cur ^= 1;

        // tail: sigma_t = softplus(z_t) + eps ; overlaps next step's LDS/ffma
#pragma unroll
        for (int r = 0; r < RPW; ++r) {
            const float z = zp[r] + fmaf(a_c, e2[r], fmaf(b_c, sig[r], c_c));
            sig[r] = fmaxf(z, 0.f) + __logf(1.f + __expf(-fabsf(z))) + EPSC;
        }

        if (lane == (t & 31)) {
#pragma unroll
            for (int r = 0; r < RPW; ++r) sbuf[r] = sig[r];
        }
        if ((t & 31) == 31) {
            const int base = t & ~31;
#pragma unroll
            for (int r = 0; r < RPW; ++r) orow[r][base + lane] = sbuf[r];
        }
    }
}

extern "C" void kernel_launch(void* const* d_in, const int* in_sizes, int n_in,
                              void* d_out, int out_size) {
    (void)in_sizes; (void)n_in; (void)out_size;
    rnn_garch_kernel<<<NBLK, NT>>>(
        (const float*)d_in[0],   // residuals
        (const float*)d_in[1],   // W_ih_w
        (const float*)d_in[2],   // W_ih_b
        (const float*)d_in[3],   // W_hh_w
        (const float*)d_in[4],   // W_hh_b
        (const float*)d_in[5],   // fc_w
        (const float*)d_in[6],   // fc_b
        (float*)d_out);
}

// round 11
// speedup vs baseline: 1.1194x; 1.1194x over previous
#include <cuda_runtime.h>
#include <cstdint>

#define SEQ   2048
#define HID   64
#define NROWS 2048
#define EPSC  1e-6f
#define WPB   8          // warps per block
#define NT    (WPB * 32) // 256 threads
#define NBLK  (NROWS / (2 * WPB))   // 128 blocks -> 1 per SM, uniform

// Packed fp32x2 FMA / ADD (Blackwell)
__device__ __forceinline__ unsigned long long ffma2(unsigned long long a,
                                                    unsigned long long b,
                                                    unsigned long long c) {
    unsigned long long d;
    asm("fma.rn.f32x2 %0, %1, %2, %3;" : "=l"(d) : "l"(a), "l"(b), "l"(c));
    return d;
}
__device__ __forceinline__ unsigned long long fadd2(unsigned long long a,
                                                    unsigned long long b) {
    unsigned long long d;
    asm("add.rn.f32x2 %0, %1, %2;" : "=l"(d) : "l"(a), "l"(b));
    return d;
}
__device__ __forceinline__ float flo(unsigned long long a) {
    return __uint_as_float((unsigned)a);
}
__device__ __forceinline__ float fhi(unsigned long long a) {
    return __uint_as_float((unsigned)(a >> 32));
}
__device__ __forceinline__ unsigned long long packlo(float x) {
    return (unsigned long long)__float_as_uint(x);   // hi = +0.0f
}

struct WarpState {
    unsigned long long W0[32], W1[32];
    float wih_e0, wih_s0, wih_e1, wih_s1, bias0, bias1;
    float a_c, b_c, c_c, g0, g1;
    float h00, h01, h10, h11;       // register copy of h_{t-1} (this lane's rows)
    float sig0, sig1;
    float rbuf0, rbuf1;             // current 32-step eps group
    float rnext0, rnext1;           // prefetched next group
    float sbuf0, sbuf1;
};

// One recurrence step. Loop-carried spine: merge -> +i -> STS -> SYNC -> LDS
// -> ffma stream. sigma (z-shuffles + softplus) is computed OFF the spine:
// produced right after the previous merge, consumed only by the late i-add.
__device__ __forceinline__ void step(WarpState& S, int t, int lane,
                                     const float* __restrict__ rrow0,
                                     const float* __restrict__ rrow1,
                                     float* __restrict__ orow0,
                                     float* __restrict__ orow1,
                                     const float* pr0, const float* pr1,
                                     float* pw0, float* pw1) {
    const int j  = lane;
    const int j2 = lane + 32;
    const int tm1 = t - 1;
    const int sl  = tm1 & 31;

    if (sl == 0) { S.rbuf0 = S.rnext0; S.rbuf1 = S.rnext1; }
    const float eps0 = __shfl_sync(0xffffffffu, S.rbuf0, sl);
    const float eps1 = __shfl_sync(0xffffffffu, S.rbuf1, sl);
    if (sl == 16) {                       // prefetch next group, 16 steps early
        const int base = (tm1 & ~31) + 32;
        if (base < SEQ) {
            S.rnext0 = rrow0[base + lane];
            S.rnext1 = rrow1[base + lane];
        }
    }
    const float e20 = eps0 * eps0;
    const float e21 = eps1 * eps1;

    // ---- matvec: chains initialized with BIAS ONLY (constant -> no wait) ----
    unsigned long long a00 = packlo(S.bias0), b00 = 0ull;
    unsigned long long a01 = packlo(S.bias1), b01 = 0ull;
    unsigned long long a10 = packlo(S.bias0), b10 = 0ull;
    unsigned long long a11 = packlo(S.bias1), b11 = 0ull;
    const ulonglong2* hb0 = reinterpret_cast<const ulonglong2*>(pr0);
    const ulonglong2* hb1 = reinterpret_cast<const ulonglong2*>(pr1);
#pragma unroll
    for (int p = 0; p < 16; ++p) {
        const ulonglong2 hv0 = hb0[p];
        const ulonglong2 hv1 = hb1[p];
        a00 = ffma2(hv0.x, S.W0[2 * p],     a00);
        b00 = ffma2(hv0.y, S.W0[2 * p + 1], b00);
        a01 = ffma2(hv0.x, S.W1[2 * p],     a01);
        b01 = ffma2(hv0.y, S.W1[2 * p + 1], b01);
        a10 = ffma2(hv1.x, S.W0[2 * p],     a10);
        b10 = ffma2(hv1.y, S.W0[2 * p + 1], b10);
        a11 = ffma2(hv1.x, S.W1[2 * p],     a11);
        b11 = ffma2(hv1.y, S.W1[2 * p + 1], b11);
    }

    // z shuffle-reduce from h_{t-1} registers — fully off the spine
    float zp0 = fmaf(S.g0, S.h00, S.g1 * S.h01);
    float zp1 = fmaf(S.g0, S.h10, S.g1 * S.h11);
#pragma unroll
    for (int o = 16; o; o >>= 1) {
        zp0 += __shfl_xor_sync(0xffffffffu, zp0, o);
        zp1 += __shfl_xor_sync(0xffffffffu, zp1, o);
    }
    const float z0 = zp0 + fmaf(S.a_c, e20, fmaf(S.b_c, S.sig0, S.c_c));
    const float z1 = zp1 + fmaf(S.a_c, e21, fmaf(S.b_c, S.sig1, S.c_c));

    // input-side terms: depend on sig_{t-1} (ready long before the chain ends)
    const float i00 = fmaf(e20, S.wih_e0, S.sig0 * S.wih_s0);
    const float i01 = fmaf(e20, S.wih_e1, S.sig0 * S.wih_s1);
    const float i10 = fmaf(e21, S.wih_e0, S.sig1 * S.wih_s0);
    const float i11 = fmaf(e21, S.wih_e1, S.sig1 * S.wih_s1);

    // sigma_t from z (off the spine; consumed next step as a late add)
    S.sig0 = fmaxf(z0, 0.f) + __logf(1.f + __expf(-fabsf(z0))) + EPSC;
    S.sig1 = fmaxf(z1, 0.f) + __logf(1.f + __expf(-fabsf(z1))) + EPSC;

    // merge chains, late i-add, publish h_t
    unsigned long long m;
    m = fadd2(a00, b00); S.h00 = (i00 + flo(m)) + fhi(m);
    m = fadd2(a01, b01); S.h01 = (i01 + flo(m)) + fhi(m);
    m = fadd2(a10, b10); S.h10 = (i10 + flo(m)) + fhi(m);
    m = fadd2(a11, b11); S.h11 = (i11 + flo(m)) + fhi(m);

    pw0[j] = S.h00; pw0[j2] = S.h01;
    pw1[j] = S.h10; pw1[j2] = S.h11;
    __syncwarp();

    // output staging (cheap, off the spine)
    if (lane == (t & 31)) { S.sbuf0 = S.sig0; S.sbuf1 = S.sig1; }
    if ((t & 31) == 31) {
        orow0[(t & ~31) + lane] = S.sbuf0;
        orow1[(t & ~31) + lane] = S.sbuf1;
    }
}

__global__ void __launch_bounds__(NT, 1)
rnn_garch_kernel(const float* __restrict__ resid,
                 const float* __restrict__ Wih,
                 const float* __restrict__ bih,
                 const float* __restrict__ Whh,
                 const float* __restrict__ bhh,
                 const float* __restrict__ fcw,
                 const float* __restrict__ fcb_p,
                 float* __restrict__ out) {
    __shared__ __align__(16) float hsh[WPB][2][2][HID];

    const int lane = threadIdx.x & 31;
    const int wid  = threadIdx.x >> 5;
    const int gw   = blockIdx.x * WPB + wid;
    const int r0   = 2 * gw;
    const int r1   = 2 * gw + 1;
    const int j  = lane;
    const int j2 = lane + 32;

    WarpState S;

    {
        const ulonglong2* wr0 = reinterpret_cast<const ulonglong2*>(Whh + j  * HID);
        const ulonglong2* wr1 = reinterpret_cast<const ulonglong2*>(Whh + j2 * HID);
#pragma unroll
        for (int i = 0; i < 16; ++i) {
            ulonglong2 a = wr0[i]; S.W0[2 * i] = a.x; S.W0[2 * i + 1] = a.y;
            ulonglong2 c = wr1[i]; S.W1[2 * i] = c.x; S.W1[2 * i + 1] = c.y;
        }
    }
    S.wih_e0 = Wih[2 * j];  S.wih_s0 = Wih[2 * j + 1];
    S.wih_e1 = Wih[2 * j2]; S.wih_s1 = Wih[2 * j2 + 1];
    S.bias0  = bih[j]  + bhh[j];
    S.bias1  = bih[j2] + bhh[j2];

    // z-trick constants: z_t = g.h_{t-1} + a*e2_t + b*sig_{t-1} + c
    {
        const float fcj = fcw[j], fcj2 = fcw[j2];
        float pa = fcj * S.wih_e0 + fcj2 * S.wih_e1;
        float pb = fcj * S.wih_s0 + fcj2 * S.wih_s1;
        float pc = fcj * S.bias0  + fcj2 * S.bias1;
#pragma unroll
        for (int o = 16; o; o >>= 1) {
            pa += __shfl_xor_sync(0xffffffffu, pa, o);
            pb += __shfl_xor_sync(0xffffffffu, pb, o);
            pc += __shfl_xor_sync(0xffffffffu, pc, o);
        }
        S.a_c = pa; S.b_c = pb; S.c_c = pc + fcb_p[0];
    }

    // g = W_hh^T fc
    S.g0 = 0.f; S.g1 = 0.f;
#pragma unroll 8
    for (int l = 0; l < HID; ++l) {
        const float f = fcw[l];
        S.g0 = fmaf(f, Whh[l * HID + j],  S.g0);
        S.g1 = fmaf(f, Whh[l * HID + j2], S.g1);
    }

    const float* rrow0 = resid + (size_t)r0 * SEQ;
    const float* rrow1 = resid + (size_t)r1 * SEQ;
    float*       orow0 = out   + (size_t)r0 * SEQ;
    float*       orow1 = out   + (size_t)r1 * SEQ;

    // sigma0 = unbiased row variance
    {
        float s1a = 0.f, s2a = 0.f, s1b = 0.f, s2b = 0.f;
        const float4* ra = reinterpret_cast<const float4*>(rrow0);
        const float4* rb = reinterpret_cast<const float4*>(rrow1);
#pragma unroll 4
        for (int i = lane; i < SEQ / 4; i += 32) {
            float4 v = ra[i];
            s1a += (v.x + v.y) + (v.z + v.w);
            s2a += v.x * v.x + v.y * v.y + v.z * v.z + v.w * v.w;
            float4 u = rb[i];
            s1b += (u.x + u.y) + (u.z + u.w);
            s2b += u.x * u.x + u.y * u.y + u.z * u.z + u.w * u.w;
        }
#pragma unroll
        for (int o = 16; o; o >>= 1) {
            s1a += __shfl_xor_sync(0xffffffffu, s1a, o);
            s2a += __shfl_xor_sync(0xffffffffu, s2a, o);
            s1b += __shfl_xor_sync(0xffffffffu, s1b, o);
            s2b += __shfl_xor_sync(0xffffffffu, s2b, o);
        }
        S.sig0 = (s2a - s1a * s1a * (1.0f / SEQ)) * (1.0f / (SEQ - 1));
        S.sig1 = (s2b - s1b * s1b * (1.0f / SEQ)) * (1.0f / (SEQ - 1));
    }

    hsh[wid][0][0][j] = 0.f; hsh[wid][0][0][j2] = 0.f;
    hsh[wid][0][1][j] = 0.f; hsh[wid][0][1][j2] = 0.f;
    __syncwarp();

    S.h00 = 0.f; S.h01 = 0.f; S.h10 = 0.f; S.h11 = 0.f;
    S.sbuf0 = S.sig0; S.sbuf1 = S.sig1;
    S.rbuf0 = 0.f; S.rbuf1 = 0.f;
    S.rnext0 = rrow0[lane];            // group 0 prefetch
    S.rnext1 = rrow1[lane];

    float* bufA0 = &hsh[wid][0][0][0];
    float* bufA1 = &hsh[wid][0][1][0];
    float* bufB0 = &hsh[wid][1][0][0];
    float* bufB1 = &hsh[wid][1][1][0];

    // t = 1 : A -> B ; then 1023 pairs (B->A, A->B)
    step(S, 1, lane, rrow0, rrow1, orow0, orow1, bufA0, bufA1, bufB0, bufB1);
    for (int t = 2; t < SEQ; t += 2) {
        step(S, t,     lane, rrow0, rrow1, orow0, orow1, bufB0, bufB1, bufA0, bufA1);
        step(S, t + 1, lane, rrow0, rrow1, orow0, orow1, bufA0, bufA1, bufB0, bufB1);
    }
}

extern "C" void kernel_launch(void* const* d_in, const int* in_sizes, int n_in,
                              void* d_out, int out_size) {
    (void)in_sizes; (void)n_in; (void)out_size;
    rnn_garch_kernel<<<NBLK, NT>>>(
        (const float*)d_in[0],   // residuals
        (const float*)d_in[1],   // W_ih_w
        (const float*)d_in[2],   // W_ih_b
        (const float*)d_in[3],   // W_hh_w
        (const float*)d_in[4],   // W_hh_b
        (const float*)d_in[5],   // fc_w
        (const float*)d_in[6],   // fc_b
        (float*)d_out);
}